// round 1
// baseline (speedup 1.0000x reference)
#include <cuda_runtime.h>

// EdgeNetwork: messages[g, i] = sum_j relu( sum_f edges[g,f] * W[f, i*32+j] + b[i*32+j] ) * states[g, j]
// g in [0, 65536) flattened (batch*edge), D=32, F=16.

#define NEDGES 65536   // BS * E = 16 * 4096
#define D 32
#define F 16
#define EPB 128        // edges per block
#define NBLOCKS (NEDGES / EPB)  // 512
#define NTHREADS 256   // 8 warps; warp handles 16 edges (2 iters of 8)

// smem layout (floats): W [16*1024] | bias [1024] | edge features [128*17] (padded)
#define SMEM_FLOATS (16 * 1024 + 1024 + EPB * 17)
#define SMEM_BYTES (SMEM_FLOATS * 4)

extern __shared__ float smem[];

__global__ __launch_bounds__(NTHREADS, 1) void edge_network_kernel(
    const float* __restrict__ states,
    const float* __restrict__ edges,
    const float* __restrict__ Wg,
    const float* __restrict__ bg,
    float* __restrict__ out)
{
    float* Wsm = smem;                  // 16384 floats
    float* bsm = smem + 16 * 1024;      // 1024 floats
    float* esm = bsm + 1024;            // 128*17 floats

    const int tid = threadIdx.x;

    // --- Stage W (64KB) as float4, bias (4KB), and this block's 128 edges' features ---
    {
        float4* Wsm4 = reinterpret_cast<float4*>(Wsm);
        const float4* Wg4 = reinterpret_cast<const float4*>(Wg);
        #pragma unroll
        for (int k = 0; k < 16; k++)
            Wsm4[tid + k * 256] = Wg4[tid + k * 256];

        reinterpret_cast<float4*>(bsm)[tid] = reinterpret_cast<const float4*>(bg)[tid];
    }
    const int gbase = blockIdx.x * EPB;
    for (int idx = tid; idx < EPB * F; idx += NTHREADS) {
        int le = idx >> 4;
        int f  = idx & 15;
        esm[le * 17 + f] = edges[gbase * F + idx];
    }
    __syncthreads();

    const int warp = tid >> 5;
    const int lane = tid & 31;
    const int u = lane >> 3;   // edge-subgroup within warp (0..3)
    const int t = lane & 7;    // 4-column group within edge (0..7)

    const float4* Wsm4 = reinterpret_cast<const float4*>(Wsm);
    const float4* bsm4 = reinterpret_cast<const float4*>(bsm);

    // Each warp: 16 edges, processed as 2 groups of 8 (edges leA = base+u, leB = base+u+4)
    for (int it = 0; it < 2; it++) {
        const int le0 = warp * 16 + it * 8;
        const int leA = le0 + u;
        const int leB = le0 + u + 4;
        const int gA = gbase + leA;
        const int gB = gbase + leB;

        // Edge features into registers (conflict-free: pitch-17 rows)
        float eA[F], eB[F];
        #pragma unroll
        for (int f = 0; f < F; f++) {
            eA[f] = esm[leA * 17 + f];
            eB[f] = esm[leB * 17 + f];
        }
        // State fragments (coalesced 128B per u-group)
        const float4 sA = *reinterpret_cast<const float4*>(states + gA * D + 4 * t);
        const float4 sB = *reinterpret_cast<const float4*>(states + gB * D + 4 * t);

        #pragma unroll 4
        for (int i = 0; i < D; i++) {
            const float4 bb = bsm4[i * 8 + t];
            float aAx = bb.x, aAy = bb.y, aAz = bb.z, aAw = bb.w;
            float aBx = bb.x, aBy = bb.y, aBz = bb.z, aBw = bb.w;

            const float4* wp = Wsm4 + i * 8 + t;
            #pragma unroll
            for (int f = 0; f < F; f++) {
                const float4 w = wp[f * 256];  // broadcast across u, conflict-free across t
                aAx = fmaf(eA[f], w.x, aAx);
                aAy = fmaf(eA[f], w.y, aAy);
                aAz = fmaf(eA[f], w.z, aAz);
                aAw = fmaf(eA[f], w.w, aAw);
                aBx = fmaf(eB[f], w.x, aBx);
                aBy = fmaf(eB[f], w.y, aBy);
                aBz = fmaf(eB[f], w.z, aBz);
                aBw = fmaf(eB[f], w.w, aBw);
            }

            // ReLU + partial dot with state fragment
            float dA = fmaxf(aAx, 0.f) * sA.x;
            dA = fmaf(fmaxf(aAy, 0.f), sA.y, dA);
            dA = fmaf(fmaxf(aAz, 0.f), sA.z, dA);
            dA = fmaf(fmaxf(aAw, 0.f), sA.w, dA);
            float dB = fmaxf(aBx, 0.f) * sB.x;
            dB = fmaf(fmaxf(aBy, 0.f), sB.y, dB);
            dB = fmaf(fmaxf(aBz, 0.f), sB.z, dB);
            dB = fmaf(fmaxf(aBw, 0.f), sB.w, dB);

            // Reduce across the 8-lane column group (butterfly -> all lanes hold m_i)
            dA += __shfl_xor_sync(0xffffffffu, dA, 1);
            dA += __shfl_xor_sync(0xffffffffu, dA, 2);
            dA += __shfl_xor_sync(0xffffffffu, dA, 4);
            dB += __shfl_xor_sync(0xffffffffu, dB, 1);
            dB += __shfl_xor_sync(0xffffffffu, dB, 2);
            dB += __shfl_xor_sync(0xffffffffu, dB, 4);

            if (t == (i & 7)) {
                out[gA * D + i] = dA;
                out[gB * D + i] = dB;
            }
        }
    }
}

extern "C" void kernel_launch(void* const* d_in, const int* in_sizes, int n_in,
                              void* d_out, int out_size)
{
    const float* states = (const float*)d_in[0];  // [16, 4096, 32]
    const float* edges  = (const float*)d_in[1];  // [16, 4096, 16]
    const float* W      = (const float*)d_in[2];  // [16, 1024]
    const float* b      = (const float*)d_in[3];  // [1024]
    float* out          = (float*)d_out;          // [16, 4096, 32]

    (void)in_sizes; (void)n_in; (void)out_size;

    cudaFuncSetAttribute(edge_network_kernel,
                         cudaFuncAttributeMaxDynamicSharedMemorySize, SMEM_BYTES);
    edge_network_kernel<<<NBLOCKS, NTHREADS, SMEM_BYTES>>>(states, edges, W, b, out);
}

// round 2
// speedup vs baseline: 1.2722x; 1.2722x over previous
#include <cuda_runtime.h>

// EdgeNetwork: messages[g, i] = sum_j relu( sum_f edges[g,f]*W[f, i*32+j] + b[i*32+j] ) * states[g, j]
// g in [0, 65536), D=32, F=16.
//
// Strategy: W slice register-resident per thread. Thread (warp w, u=lane>>3, t=lane&7)
// owns row i = 4w+u and columns 4t..4t+3 -> W regs = 16 float4 (64 regs), loaded once.
// All 128 edges of the block stream through the registers; smem only serves edge
// features (broadcast) and state fragments.

#define D 32
#define F 16
#define EPB 128
#define NEDGES 65536
#define NBLOCKS (NEDGES / EPB)   // 512
#define NTHREADS 256             // 8 warps: warp w covers i in [4w, 4w+4)

__global__ __launch_bounds__(NTHREADS, 2) void edge_network_kernel(
    const float* __restrict__ states,
    const float* __restrict__ edges,
    const float* __restrict__ Wg,
    const float* __restrict__ bg,
    float* __restrict__ out)
{
    __shared__ float4 esm[EPB * 4];  // 8 KB  : 4 float4 of edge features per edge
    __shared__ float4 ssm[EPB * 8];  // 16 KB : 8 float4 of state per edge

    const int tid = threadIdx.x;
    const int gbase = blockIdx.x * EPB;

    // --- Stage this block's edge features and states (coalesced float4) ---
    {
        const float4* eg4 = reinterpret_cast<const float4*>(edges + (size_t)gbase * F);
        #pragma unroll
        for (int k = 0; k < 2; k++)
            esm[tid + k * 256] = eg4[tid + k * 256];

        const float4* sg4 = reinterpret_cast<const float4*>(states + (size_t)gbase * D);
        #pragma unroll
        for (int k = 0; k < 4; k++)
            ssm[tid + k * 256] = sg4[tid + k * 256];
    }

    const int warp = tid >> 5;
    const int lane = tid & 31;
    const int u = lane >> 3;              // 0..3 : row within warp's quad
    const int t = lane & 7;               // 0..7 : 4-column group
    const int i = warp * 4 + u;           // output row owned by this thread
    const int colbase = i * D + 4 * t;    // column offset in [0, 1024)

    // --- W slice + bias into registers (one-time; W is L2-resident, 64 KB) ---
    float4 wr[F];
    #pragma unroll
    for (int f = 0; f < F; f++)
        wr[f] = *reinterpret_cast<const float4*>(Wg + f * (D * D) + colbase);
    const float4 bb = *reinterpret_cast<const float4*>(bg + colbase);

    __syncthreads();

    // --- Stream edges through the register-resident W ---
    for (int le = 0; le < EPB; le++) {
        const float4 e0 = esm[le * 4 + 0];   // broadcast across warp
        const float4 e1 = esm[le * 4 + 1];
        const float4 e2 = esm[le * 4 + 2];
        const float4 e3 = esm[le * 4 + 3];
        const float4 s  = ssm[le * 8 + t];   // 128B, conflict-free, broadcast across u

        float ef[F] = { e0.x, e0.y, e0.z, e0.w,
                        e1.x, e1.y, e1.z, e1.w,
                        e2.x, e2.y, e2.z, e2.w,
                        e3.x, e3.y, e3.z, e3.w };

        float ax = bb.x, ay = bb.y, az = bb.z, aw = bb.w;
        #pragma unroll
        for (int f = 0; f < F; f++) {
            ax = fmaf(ef[f], wr[f].x, ax);
            ay = fmaf(ef[f], wr[f].y, ay);
            az = fmaf(ef[f], wr[f].z, az);
            aw = fmaf(ef[f], wr[f].w, aw);
        }

        // ReLU + partial dot with the state fragment
        float d = fmaxf(ax, 0.f) * s.x;
        d = fmaf(fmaxf(ay, 0.f), s.y, d);
        d = fmaf(fmaxf(az, 0.f), s.z, d);
        d = fmaf(fmaxf(aw, 0.f), s.w, d);

        // Reduce over the 8-lane column group (xor 1/2/4 stays within the t-group)
        d += __shfl_xor_sync(0xffffffffu, d, 1);
        d += __shfl_xor_sync(0xffffffffu, d, 2);
        d += __shfl_xor_sync(0xffffffffu, d, 4);

        // Lanes with t==u store: 4 lanes/warp, 16 contiguous bytes (i = 4w..4w+3)
        if (t == u)
            out[(size_t)(gbase + le) * D + i] = d;
    }
}

extern "C" void kernel_launch(void* const* d_in, const int* in_sizes, int n_in,
                              void* d_out, int out_size)
{
    const float* states = (const float*)d_in[0];  // [16, 4096, 32]
    const float* edges  = (const float*)d_in[1];  // [16, 4096, 16]
    const float* W      = (const float*)d_in[2];  // [16, 1024]
    const float* b      = (const float*)d_in[3];  // [1024]
    float* out          = (float*)d_out;          // [16, 4096, 32]

    (void)in_sizes; (void)n_in; (void)out_size;

    edge_network_kernel<<<NBLOCKS, NTHREADS>>>(states, edges, W, b, out);
}

// round 3
// speedup vs baseline: 1.4287x; 1.1230x over previous
#include <cuda_runtime.h>

// EdgeNetwork: messages[g,i] = sum_j relu( sum_f edges[g,f]*W[f, i*32+j] + b[i*32+j] ) * states[g,j]
// g in [0, 65536), D=32, F=16.
//
// Round 3: packed fp32 math. Inner MLP uses fma.rn.f32x2 (FFMA2): one issue slot
// per 2 MACs, bit-exact vs scalar FFMA. W slice register-resident as packed pairs;
// edge features pre-duplicated {e,e} in smem so no per-edge packing instructions.

#define D 32
#define F 16
#define EPB 128
#define NEDGES 65536
#define NBLOCKS (NEDGES / EPB)   // 512
#define NTHREADS 256             // 8 warps: warp w covers rows i in [4w, 4w+4)

typedef unsigned long long u64;

__device__ __forceinline__ u64 dup_f32x2(float x) {
    u64 r;
    asm("mov.b64 %0, {%1, %1};" : "=l"(r) : "f"(x));
    return r;
}
__device__ __forceinline__ u64 pack_f32x2(float lo, float hi) {
    u64 r;
    asm("mov.b64 %0, {%1, %2};" : "=l"(r) : "f"(lo), "f"(hi));
    return r;
}
__device__ __forceinline__ void unpack_f32x2(u64 v, float& lo, float& hi) {
    asm("mov.b64 {%0, %1}, %2;" : "=f"(lo), "=f"(hi) : "l"(v));
}
__device__ __forceinline__ void fma2(u64& acc, u64 a, u64 b) {
    asm("fma.rn.f32x2 %0, %1, %2, %0;" : "+l"(acc) : "l"(a), "l"(b));
}

__global__ __launch_bounds__(NTHREADS, 2) void edge_network_kernel(
    const float* __restrict__ states,
    const float* __restrict__ edges,
    const float* __restrict__ Wg,
    const float* __restrict__ bg,
    float* __restrict__ out)
{
    // Duplicated edge features: esm2[le*8 + q] = { {e[2q],e[2q]}, {e[2q+1],e[2q+1]} }
    __shared__ ulonglong2 esm2[EPB * 8];   // 16 KB
    __shared__ float4     ssm[EPB * 8];    // 16 KB

    const int tid = threadIdx.x;
    const int gbase = blockIdx.x * EPB;

    // --- Stage states (coalesced float4) and edge features (duplicated pairs) ---
    {
        const float4* sg4 = reinterpret_cast<const float4*>(states + (size_t)gbase * D);
        #pragma unroll
        for (int k = 0; k < 4; k++)
            ssm[tid + k * 256] = sg4[tid + k * 256];

        const float4* eg4 = reinterpret_cast<const float4*>(edges + (size_t)gbase * F);
        #pragma unroll
        for (int k = 0; k < 2; k++) {
            int idx = tid + k * 256;          // over 512 float4 (4 per edge)
            float4 e = eg4[idx];
            int le = idx >> 2;
            int q  = idx & 3;                 // quarter: features [4q, 4q+4)
            esm2[le * 8 + q * 2 + 0] = make_ulonglong2(dup_f32x2(e.x), dup_f32x2(e.y));
            esm2[le * 8 + q * 2 + 1] = make_ulonglong2(dup_f32x2(e.z), dup_f32x2(e.w));
        }
    }

    const int warp = tid >> 5;
    const int lane = tid & 31;
    const int u = lane >> 3;              // 0..3 : row within warp's quad
    const int t = lane & 7;               // 0..7 : 4-column group
    const int i = warp * 4 + u;           // output row owned by this thread
    const int colbase = i * D + 4 * t;

    // --- W slice + bias into packed registers (one-time) ---
    u64 w01[F], w23[F];
    #pragma unroll
    for (int f = 0; f < F; f++) {
        float4 w = *reinterpret_cast<const float4*>(Wg + f * (D * D) + colbase);
        w01[f] = pack_f32x2(w.x, w.y);
        w23[f] = pack_f32x2(w.z, w.w);
    }
    const float4 bbv = *reinterpret_cast<const float4*>(bg + colbase);
    const u64 b01 = pack_f32x2(bbv.x, bbv.y);
    const u64 b23 = pack_f32x2(bbv.z, bbv.w);

    __syncthreads();

    // --- Stream edges through register-resident packed W ---
    for (int le = 0; le < EPB; le++) {
        const ulonglong2* ep = esm2 + le * 8;
        const float4 s = ssm[le * 8 + t];   // conflict-free, broadcast across u

        u64 a01 = b01, a23 = b23;
        #pragma unroll
        for (int q = 0; q < 8; q++) {
            ulonglong2 ee = ep[q];          // LDS.128 broadcast: features 2q, 2q+1 duplicated
            fma2(a01, ee.x, w01[2 * q + 0]);
            fma2(a23, ee.x, w23[2 * q + 0]);
            fma2(a01, ee.y, w01[2 * q + 1]);
            fma2(a23, ee.y, w23[2 * q + 1]);
        }

        float ax, ay, az, aw;
        unpack_f32x2(a01, ax, ay);
        unpack_f32x2(a23, az, aw);

        // ReLU + partial dot with the state fragment
        float d = fmaxf(ax, 0.f) * s.x;
        d = fmaf(fmaxf(ay, 0.f), s.y, d);
        d = fmaf(fmaxf(az, 0.f), s.z, d);
        d = fmaf(fmaxf(aw, 0.f), s.w, d);

        // Reduce across the 8-lane column group
        d += __shfl_xor_sync(0xffffffffu, d, 1);
        d += __shfl_xor_sync(0xffffffffu, d, 2);
        d += __shfl_xor_sync(0xffffffffu, d, 4);

        if (t == u)
            out[(size_t)(gbase + le) * D + i] = d;
    }
}

extern "C" void kernel_launch(void* const* d_in, const int* in_sizes, int n_in,
                              void* d_out, int out_size)
{
    const float* states = (const float*)d_in[0];  // [16, 4096, 32]
    const float* edges  = (const float*)d_in[1];  // [16, 4096, 16]
    const float* W      = (const float*)d_in[2];  // [16, 1024]
    const float* b      = (const float*)d_in[3];  // [1024]
    float* out          = (float*)d_out;          // [16, 4096, 32]

    (void)in_sizes; (void)n_in; (void)out_size;

    edge_network_kernel<<<NBLOCKS, NTHREADS>>>(states, edges, W, b, out);
}

// round 5
// speedup vs baseline: 1.6897x; 1.1827x over previous
#include <cuda_runtime.h>
#include <cstdint>

// EdgeNetwork via mma.sync m16n8k8 tf32 with error-compensated split.
// H = E@W + b ; messages[g,i] = sum_j relu(H[g, 32i+j]) * s[g,j]
// E = Eh + El (tf32 each), W = Wh + Wl.  H ~= EhWh + EhWl + ElWh (drop ElWl ~2^-22).

#define NTHREADS 256

// smem byte offsets
#define SM_WPH  0                       // [2][512][4] float2 = 32KB  (Wh, fragment-permuted)
#define SM_WPL  32768                   // 32KB (Wl)
#define SM_EPH  65536                   // [2][128][4] float2 = 8KB  (Eh)
#define SM_EPL  (65536 + 8192)          // 8KB (El)
#define SM_SP   (65536 + 16384)         // [4][128][4] float2 = 16KB (states, permuted)
#define SM_BIAS (SM_SP + 16384)         // 512 floats = 2KB
#define SM_TOTAL (SM_BIAS + 2048)       // 100,352 B -> 2 CTAs/SM

// Pre-split W in fragment-permuted layout: float [2][1024][4][2]
//   idx = ((h*1024 + n)*4 + q)*2 + sel  where f = h*8 + sel*4 + q
__device__ float d_Wph[16384];
__device__ float d_Wpl[16384];

__device__ __forceinline__ float tf32_rna(float x) {
    uint32_t r; asm("cvt.rna.tf32.f32 %0, %1;" : "=r"(r) : "f"(x));
    return __uint_as_float(r);
}

__global__ void prep_w(const float* __restrict__ W) {
    int idx = blockIdx.x * 256 + threadIdx.x;       // 0..16383 over [f][n]
    float v = W[idx];
    float hi = tf32_rna(v);
    float lo = tf32_rna(v - hi);
    int f = idx >> 10, n = idx & 1023;
    int h = f >> 3, r8 = f & 7, q = r8 & 3, sel = r8 >> 2;
    int pos = ((h * 1024 + n) * 4 + q) * 2 + sel;
    d_Wph[pos] = hi;
    d_Wpl[pos] = lo;
}

// m16n8k8 tf32 mma. a_lo = A rows g (k=q, k=q+4), a_hi = rows g+8; b = (B[q][n], B[q+4][n]).
__device__ __forceinline__ void mma8(float& d0, float& d1, float& d2, float& d3,
                                     float2 a_lo, float2 a_hi, float2 b) {
    asm volatile(
        "mma.sync.aligned.m16n8k8.row.col.f32.tf32.tf32.f32 "
        "{%0,%1,%2,%3}, {%4,%5,%6,%7}, {%8,%9}, {%0,%1,%2,%3};"
        : "+f"(d0), "+f"(d1), "+f"(d2), "+f"(d3)
        : "r"(__float_as_uint(a_lo.x)), "r"(__float_as_uint(a_hi.x)),
          "r"(__float_as_uint(a_lo.y)), "r"(__float_as_uint(a_hi.y)),
          "r"(__float_as_uint(b.x)),    "r"(__float_as_uint(b.y)));
}

__global__ __launch_bounds__(NTHREADS, 2) void edge_net_mma(
    const float* __restrict__ states,
    const float* __restrict__ edges,
    const float* __restrict__ bg,
    float* __restrict__ out)
{
    extern __shared__ char sm[];
    const float2* WPH = (const float2*)(sm + SM_WPH);   // [h][512][4]
    const float2* WPL = (const float2*)(sm + SM_WPL);
    const float2* EPH = (const float2*)(sm + SM_EPH);   // [h][128][4]
    const float2* EPL = (const float2*)(sm + SM_EPL);
    const float2* SP  = (const float2*)(sm + SM_SP);    // [a][128][4]
    float* BS = (float*)(sm + SM_BIAS);

    const int tid = threadIdx.x;
    const int eb = blockIdx.x & 511;        // edge block (128 edges)
    const int cb = blockIdx.x >> 9;         // column half (512 cols)
    const int gbase = eb * 128;
    const int col0 = cb * 512;

    // ---- Stage W slices (float4 copies of prepped arrays; L2-resident) ----
    {
        const float4* srcH = (const float4*)d_Wph;
        const float4* srcL = (const float4*)d_Wpl;
        float4* dstH = (float4*)(sm + SM_WPH);
        float4* dstL = (float4*)(sm + SM_WPL);
        #pragma unroll
        for (int k = 0; k < 8; k++) {
            int idx = tid + k * 256;        // 0..2047
            int h = idx >> 10, r = idx & 1023;
            dstH[h * 1024 + r] = srcH[h * 2048 + col0 * 2 + r];
            dstL[h * 1024 + r] = srcL[h * 2048 + col0 * 2 + r];
        }
    }
    // bias slice
    BS[tid] = bg[col0 + tid];
    BS[tid + 256] = bg[col0 + tid + 256];

    // ---- Stage + split edges (fragment-permuted) ----
    #pragma unroll
    for (int k = 0; k < 8; k++) {
        int idx = tid + k * 256;            // 0..2047 over [row][f]
        int row = idx >> 4, f = idx & 15;
        float v = edges[(size_t)gbase * 16 + idx];
        float hi = tf32_rna(v);
        float lo = tf32_rna(v - hi);
        int h = f >> 3, r8 = f & 7, q = r8 & 3, sel = r8 >> 2;
        int pos = ((h * 128 + row) * 4 + q) * 2 + sel;
        ((float*)(sm + SM_EPH))[pos] = hi;
        ((float*)(sm + SM_EPL))[pos] = lo;
    }
    // ---- Stage states (permuted: SP[a][row][q] = {s[row][8a+2q], s[row][8a+2q+1]}) ----
    #pragma unroll
    for (int k = 0; k < 16; k++) {
        int idx = tid + k * 256;            // 0..4095 over [row][j]
        int row = idx >> 5, j = idx & 31;
        float v = states[(size_t)gbase * 32 + idx];
        int a = j >> 3, rem = j & 7, q2 = rem >> 1, sel = rem & 1;
        ((float*)(sm + SM_SP))[((a * 128 + row) * 4 + q2) * 2 + sel] = v;
    }
    __syncthreads();

    const int w = tid >> 5, lane = tid & 31;
    const int g = lane >> 2;                // fragment groupID (row / B-col)
    const int q = lane & 3;                 // threadID-in-group (k / D-col pair)

    float mm[2][2] = {{0.f, 0.f}, {0.f, 0.f}};   // [rt][row-half]

    #pragma unroll
    for (int pass = 0; pass < 4; pass++) {
        const int rb = pass * 32;

        // A fragments for 2 row-tiles (conflict-free LDS.64)
        float2 ah[2][2][2], al[2][2][2];    // [rt][h][row-half]
        #pragma unroll
        for (int rt = 0; rt < 2; rt++) {
            int row = rb + rt * 16 + g;
            #pragma unroll
            for (int h = 0; h < 2; h++) {
                ah[rt][h][0] = EPH[h * 512 + row * 4 + q];
                ah[rt][h][1] = EPH[h * 512 + (row + 8) * 4 + q];
                al[rt][h][0] = EPL[h * 512 + row * 4 + q];
                al[rt][h][1] = EPL[h * 512 + (row + 8) * 4 + q];
            }
        }

        #pragma unroll
        for (int ct = 0; ct < 8; ct++) {
            const int nl = w * 64 + ct * 8 + g;
            const float2 bh0 = WPH[nl * 4 + q];
            const float2 bh1 = WPH[2048 + nl * 4 + q];
            const float2 bl0 = WPL[nl * 4 + q];
            const float2 bl1 = WPL[2048 + nl * 4 + q];
            const float2 bias2 = *(const float2*)(BS + w * 64 + ct * 8 + 2 * q);

            float d[2][4];
            #pragma unroll
            for (int rt = 0; rt < 2; rt++) {
                d[rt][0] = bias2.x; d[rt][1] = bias2.y;
                d[rt][2] = bias2.x; d[rt][3] = bias2.y;
            }

            // 6 mma per row-tile, interleaved for 2 independent chains
            mma8(d[0][0], d[0][1], d[0][2], d[0][3], ah[0][0][0], ah[0][0][1], bh0);
            mma8(d[1][0], d[1][1], d[1][2], d[1][3], ah[1][0][0], ah[1][0][1], bh0);
            mma8(d[0][0], d[0][1], d[0][2], d[0][3], ah[0][1][0], ah[0][1][1], bh1);
            mma8(d[1][0], d[1][1], d[1][2], d[1][3], ah[1][1][0], ah[1][1][1], bh1);
            mma8(d[0][0], d[0][1], d[0][2], d[0][3], ah[0][0][0], ah[0][0][1], bl0);
            mma8(d[1][0], d[1][1], d[1][2], d[1][3], ah[1][0][0], ah[1][0][1], bl0);
            mma8(d[0][0], d[0][1], d[0][2], d[0][3], ah[0][1][0], ah[0][1][1], bl1);
            mma8(d[1][0], d[1][1], d[1][2], d[1][3], ah[1][1][0], ah[1][1][1], bl1);
            mma8(d[0][0], d[0][1], d[0][2], d[0][3], al[0][0][0], al[0][0][1], bh0);
            mma8(d[1][0], d[1][1], d[1][2], d[1][3], al[1][0][0], al[1][0][1], bh0);
            mma8(d[0][0], d[0][1], d[0][2], d[0][3], al[0][1][0], al[0][1][1], bh1);
            mma8(d[1][0], d[1][1], d[1][2], d[1][3], al[1][1][0], al[1][1][1], bh1);

            // epilogue: relu already has bias folded in via accumulator init
            const int a = ct & 3;
            #pragma unroll
            for (int rt = 0; rt < 2; rt++) {
                int row = rb + rt * 16 + g;
                float2 s0 = SP[a * 512 + row * 4 + q];
                float2 s1 = SP[a * 512 + (row + 8) * 4 + q];
                mm[rt][0] = fmaf(fmaxf(d[rt][0], 0.f), s0.x, mm[rt][0]);
                mm[rt][0] = fmaf(fmaxf(d[rt][1], 0.f), s0.y, mm[rt][0]);
                mm[rt][1] = fmaf(fmaxf(d[rt][2], 0.f), s1.x, mm[rt][1]);
                mm[rt][1] = fmaf(fmaxf(d[rt][3], 0.f), s1.y, mm[rt][1]);
            }

            if ((ct & 3) == 3) {
                const int i = cb * 16 + w * 2 + (ct >> 2);
                #pragma unroll
                for (int rt = 0; rt < 2; rt++) {
                    float v0 = mm[rt][0], v1 = mm[rt][1];
                    v0 += __shfl_xor_sync(0xffffffffu, v0, 1);
                    v0 += __shfl_xor_sync(0xffffffffu, v0, 2);
                    v1 += __shfl_xor_sync(0xffffffffu, v1, 1);
                    v1 += __shfl_xor_sync(0xffffffffu, v1, 2);
                    if (q == 0) {
                        int row = rb + rt * 16 + g;
                        out[(size_t)(gbase + row) * 32 + i] = v0;
                        out[(size_t)(gbase + row + 8) * 32 + i] = v1;
                    }
                    mm[rt][0] = 0.f; mm[rt][1] = 0.f;
                }
            }
        }
    }
}

extern "C" void kernel_launch(void* const* d_in, const int* in_sizes, int n_in,
                              void* d_out, int out_size)
{
    const float* states = (const float*)d_in[0];  // [16, 4096, 32]
    const float* edges  = (const float*)d_in[1];  // [16, 4096, 16]
    const float* W      = (const float*)d_in[2];  // [16, 1024]
    const float* b      = (const float*)d_in[3];  // [1024]
    float* out          = (float*)d_out;          // [16, 4096, 32]

    (void)in_sizes; (void)n_in; (void)out_size;

    static int configured = 0;
    if (!configured) {
        cudaFuncSetAttribute(edge_net_mma,
                             cudaFuncAttributeMaxDynamicSharedMemorySize, SM_TOTAL);
        configured = 1;
    }
    prep_w<<<64, 256>>>(W);
    edge_net_mma<<<1024, NTHREADS, SM_TOTAL>>>(states, edges, b, out);
}

// round 6
// speedup vs baseline: 2.4198x; 1.4321x over previous
#include <cuda_runtime.h>
#include <cuda_fp16.h>
#include <cstdint>

// EdgeNetwork via mma.sync m16n8k16 fp16 with error-compensated split.
// H = E@W + b ; messages[g,i] = sum_j relu(H[g, 32i+j]) * s[g,j]
// E = Eh + El (fp16 each, 22-bit combined mantissa), W = Wh + Wl.
// H ~= EhWh + EhWl + ElWh (dropped ElWl ~2^-22).

#define NTHREADS 256

// smem byte offsets
#define SM_WH   0                      // [512 cols][4 q] uint2 = 16KB
#define SM_WL   16384                  // 16KB
#define SM_EH   32768                  // [128 rows][4 q] uint2 = 4KB
#define SM_EL   36864                  // 4KB
#define SM_SP   40960                  // [4][128][4] float2 = 16KB
#define SM_BIAS 57344                  // 512 floats = 2KB
#define SM_TOTAL 59392                 // -> 3 CTAs/SM

// Pre-split W, fragment-permuted: entry [n][q] = { h2(w[2q][n],w[2q+1][n]), h2(w[2q+8][n],w[2q+9][n]) }
__device__ uint2 d_Wh[4096];
__device__ uint2 d_Wl[4096];

__device__ __forceinline__ void split16(float v, __half& hi, __half& lo) {
    hi = __float2half_rn(v);
    lo = __float2half_rn(v - __half2float(hi));
}
__device__ __forceinline__ uint32_t pack_h2(__half a, __half b) {
    __half2 h = __halves2half2(a, b);
    return *reinterpret_cast<uint32_t*>(&h);
}

__global__ void prep_w(const float* __restrict__ W) {
    int idx = blockIdx.x * 256 + threadIdx.x;   // 0..4095 over [n][q]
    int n = idx >> 2, q = idx & 3;
    __half h0, l0, h1, l1, h2v, l2, h3, l3;
    split16(W[(2 * q)     * 1024 + n], h0, l0);
    split16(W[(2 * q + 1) * 1024 + n], h1, l1);
    split16(W[(2 * q + 8) * 1024 + n], h2v, l2);
    split16(W[(2 * q + 9) * 1024 + n], h3, l3);
    d_Wh[idx] = make_uint2(pack_h2(h0, h1), pack_h2(h2v, h3));
    d_Wl[idx] = make_uint2(pack_h2(l0, l1), pack_h2(l2, l3));
}

// m16n8k16 f16->f32. arow = {a0,a2} (row g), arow8 = {a1,a3} (row g+8), b = {b0,b1}.
__device__ __forceinline__ void mma16(float& d0, float& d1, float& d2, float& d3,
                                      uint2 arow, uint2 arow8, uint2 b) {
    asm volatile(
        "mma.sync.aligned.m16n8k16.row.col.f32.f16.f16.f32 "
        "{%0,%1,%2,%3}, {%4,%5,%6,%7}, {%8,%9}, {%0,%1,%2,%3};"
        : "+f"(d0), "+f"(d1), "+f"(d2), "+f"(d3)
        : "r"(arow.x), "r"(arow8.x), "r"(arow.y), "r"(arow8.y),
          "r"(b.x), "r"(b.y));
}

__global__ __launch_bounds__(NTHREADS, 3) void edge_net_mma(
    const float* __restrict__ states,
    const float* __restrict__ edges,
    const float* __restrict__ bg,
    float* __restrict__ out)
{
    extern __shared__ char sm[];
    const uint2* WH = (const uint2*)(sm + SM_WH);
    const uint2* WL = (const uint2*)(sm + SM_WL);
    const uint2* EH = (const uint2*)(sm + SM_EH);
    const uint2* EL = (const uint2*)(sm + SM_EL);
    const float2* SP = (const float2*)(sm + SM_SP);
    float* BS = (float*)(sm + SM_BIAS);

    const int tid = threadIdx.x;
    const int eb = blockIdx.x & 511;       // edge block (128 edges)
    const int cb = blockIdx.x >> 9;        // column half (512 cols)
    const int gbase = eb * 128;
    const int col0 = cb * 512;

    // ---- Stage W slices (contiguous uint4 copies; L2-resident) ----
    {
        const uint4* srcH = (const uint4*)(d_Wh + col0 * 4);
        const uint4* srcL = (const uint4*)(d_Wl + col0 * 4);
        uint4* dstH = (uint4*)(sm + SM_WH);
        uint4* dstL = (uint4*)(sm + SM_WL);
        #pragma unroll
        for (int k = 0; k < 4; k++) {
            dstH[tid + k * 256] = srcH[tid + k * 256];
            dstL[tid + k * 256] = srcL[tid + k * 256];
        }
    }
    BS[tid] = bg[col0 + tid];
    BS[tid + 256] = bg[col0 + tid + 256];

    // ---- Stage + split edges: EH/EL[row][q] ----
    {
        const float2* er = (const float2*)(edges + (size_t)gbase * 16);
        #pragma unroll
        for (int k = 0; k < 2; k++) {
            int item = tid + k * 256;          // 0..511 over [row][q]
            int row = item >> 2, q = item & 3;
            float2 v0 = er[row * 8 + q];
            float2 v1 = er[row * 8 + q + 4];
            __half h0, l0, h1, l1, h2v, l2, h3, l3;
            split16(v0.x, h0, l0);  split16(v0.y, h1, l1);
            split16(v1.x, h2v, l2); split16(v1.y, h3, l3);
            ((uint2*)(sm + SM_EH))[item] = make_uint2(pack_h2(h0, h1), pack_h2(h2v, h3));
            ((uint2*)(sm + SM_EL))[item] = make_uint2(pack_h2(l0, l1), pack_h2(l2, l3));
        }
    }
    // ---- Stage states permuted: SP[a][row][q] = {s[row][8a+2q], s[row][8a+2q+1]} ----
    #pragma unroll
    for (int k = 0; k < 16; k++) {
        int idx = tid + k * 256;               // 0..4095 over [row][j]
        int row = idx >> 5, j = idx & 31;
        float v = states[(size_t)gbase * 32 + idx];
        int a = j >> 3, rem = j & 7, q2 = rem >> 1, sel = rem & 1;
        ((float*)(sm + SM_SP))[((a * 128 + row) * 4 + q2) * 2 + sel] = v;
    }
    __syncthreads();

    const int w = tid >> 5, lane = tid & 31;
    const int g = lane >> 2;                   // groupID: row-in-tile / B-col
    const int q = lane & 3;                    // threadID-in-group

    float mm[2][2] = {{0.f, 0.f}, {0.f, 0.f}}; // [rt][row-half]

    #pragma unroll
    for (int pass = 0; pass < 4; pass++) {
        const int rb = pass * 32;

        uint2 ah[2][2], al[2][2];              // [rt][row / row+8]
        #pragma unroll
        for (int rt = 0; rt < 2; rt++) {
            int row = rb + rt * 16 + g;
            ah[rt][0] = EH[row * 4 + q];
            ah[rt][1] = EH[(row + 8) * 4 + q];
            al[rt][0] = EL[row * 4 + q];
            al[rt][1] = EL[(row + 8) * 4 + q];
        }

        #pragma unroll
        for (int ct = 0; ct < 8; ct++) {
            const int nl = w * 64 + ct * 8 + g;
            const uint2 wh = WH[nl * 4 + q];
            const uint2 wl = WL[nl * 4 + q];
            const float2 bias2 = *(const float2*)(BS + w * 64 + ct * 8 + 2 * q);

            float d[2][4];
            #pragma unroll
            for (int rt = 0; rt < 2; rt++) {
                d[rt][0] = bias2.x; d[rt][1] = bias2.y;
                d[rt][2] = bias2.x; d[rt][3] = bias2.y;
            }

            mma16(d[0][0], d[0][1], d[0][2], d[0][3], ah[0][0], ah[0][1], wh);
            mma16(d[1][0], d[1][1], d[1][2], d[1][3], ah[1][0], ah[1][1], wh);
            mma16(d[0][0], d[0][1], d[0][2], d[0][3], ah[0][0], ah[0][1], wl);
            mma16(d[1][0], d[1][1], d[1][2], d[1][3], ah[1][0], ah[1][1], wl);
            mma16(d[0][0], d[0][1], d[0][2], d[0][3], al[0][0], al[0][1], wh);
            mma16(d[1][0], d[1][1], d[1][2], d[1][3], al[1][0], al[1][1], wh);

            // Epilogue: relu (bias pre-seeded) dot state fragment
            const int a = ct & 3;
            #pragma unroll
            for (int rt = 0; rt < 2; rt++) {
                int row = rb + rt * 16 + g;
                float2 s0 = SP[a * 512 + row * 4 + q];
                float2 s1 = SP[a * 512 + (row + 8) * 4 + q];
                mm[rt][0] = fmaf(fmaxf(d[rt][0], 0.f), s0.x, mm[rt][0]);
                mm[rt][0] = fmaf(fmaxf(d[rt][1], 0.f), s0.y, mm[rt][0]);
                mm[rt][1] = fmaf(fmaxf(d[rt][2], 0.f), s1.x, mm[rt][1]);
                mm[rt][1] = fmaf(fmaxf(d[rt][3], 0.f), s1.y, mm[rt][1]);
            }

            if ((ct & 3) == 3) {
                const int i = cb * 16 + w * 2 + (ct >> 2);
                #pragma unroll
                for (int rt = 0; rt < 2; rt++) {
                    float v0 = mm[rt][0], v1 = mm[rt][1];
                    v0 += __shfl_xor_sync(0xffffffffu, v0, 1);
                    v0 += __shfl_xor_sync(0xffffffffu, v0, 2);
                    v1 += __shfl_xor_sync(0xffffffffu, v1, 1);
                    v1 += __shfl_xor_sync(0xffffffffu, v1, 2);
                    if (q == 0) {
                        int row = rb + rt * 16 + g;
                        out[(size_t)(gbase + row) * 32 + i] = v0;
                        out[(size_t)(gbase + row + 8) * 32 + i] = v1;
                    }
                    mm[rt][0] = 0.f; mm[rt][1] = 0.f;
                }
            }
        }
    }
}

extern "C" void kernel_launch(void* const* d_in, const int* in_sizes, int n_in,
                              void* d_out, int out_size)
{
    const float* states = (const float*)d_in[0];  // [16, 4096, 32]
    const float* edges  = (const float*)d_in[1];  // [16, 4096, 16]
    const float* W      = (const float*)d_in[2];  // [16, 1024]
    const float* b      = (const float*)d_in[3];  // [1024]
    float* out          = (float*)d_out;          // [16, 4096, 32]

    (void)in_sizes; (void)n_in; (void)out_size;

    static int configured = 0;
    if (!configured) {
        cudaFuncSetAttribute(edge_net_mma,
                             cudaFuncAttributeMaxDynamicSharedMemorySize, SM_TOTAL);
        configured = 1;
    }
    prep_w<<<16, 256>>>(W);
    edge_net_mma<<<1024, NTHREADS, SM_TOTAL>>>(states, edges, b, out);
}

// round 7
// speedup vs baseline: 2.7152x; 1.1221x over previous
#include <cuda_runtime.h>
#include <cuda_fp16.h>
#include <cstdint>

// EdgeNetwork via mma.sync m16n8k16 fp16 error-compensated split.
// H = E@W + b ; messages[g,i] = sum_j relu(H[g, 32i+j]) * s[g,j]
// E = Eh + El, W = Wh + Wl (fp16 each). H ~= EhWh + EhWl + ElWh.
// R7: W/bias fragments register-resident (loaded from L2 once); a-outer loop halves
// state-fragment smem traffic; smem = 24KB.

#define NTHREADS 256

// smem byte offsets
#define SM_EH   0                      // [128 rows][4 q] uint2 = 4KB
#define SM_EL   4096                   // 4KB
#define SM_SP   8192                   // [4][128][4] float2 = 16KB
#define SM_TOTAL 24576

// Pre-split W, fragment-permuted: entry [n][q] = { h2(w[2q][n],w[2q+1][n]), h2(w[2q+8][n],w[2q+9][n]) }
__device__ uint2 d_Wh[4096];
__device__ uint2 d_Wl[4096];

__device__ __forceinline__ void split16(float v, __half& hi, __half& lo) {
    hi = __float2half_rn(v);
    lo = __float2half_rn(v - __half2float(hi));
}
__device__ __forceinline__ uint32_t pack_h2(__half a, __half b) {
    __half2 h = __halves2half2(a, b);
    return *reinterpret_cast<uint32_t*>(&h);
}

__global__ void prep_w(const float* __restrict__ W) {
    int idx = blockIdx.x * 256 + threadIdx.x;   // 0..4095 over [n][q]
    int n = idx >> 2, q = idx & 3;
    __half h0, l0, h1, l1, h2v, l2, h3, l3;
    split16(W[(2 * q)     * 1024 + n], h0, l0);
    split16(W[(2 * q + 1) * 1024 + n], h1, l1);
    split16(W[(2 * q + 8) * 1024 + n], h2v, l2);
    split16(W[(2 * q + 9) * 1024 + n], h3, l3);
    d_Wh[idx] = make_uint2(pack_h2(h0, h1), pack_h2(h2v, h3));
    d_Wl[idx] = make_uint2(pack_h2(l0, l1), pack_h2(l2, l3));
}

__device__ __forceinline__ void mma16(float& d0, float& d1, float& d2, float& d3,
                                      uint2 arow, uint2 arow8, uint2 b) {
    asm volatile(
        "mma.sync.aligned.m16n8k16.row.col.f32.f16.f16.f32 "
        "{%0,%1,%2,%3}, {%4,%5,%6,%7}, {%8,%9}, {%0,%1,%2,%3};"
        : "+f"(d0), "+f"(d1), "+f"(d2), "+f"(d3)
        : "r"(arow.x), "r"(arow8.x), "r"(arow.y), "r"(arow8.y),
          "r"(b.x), "r"(b.y));
}

__global__ __launch_bounds__(NTHREADS, 2) void edge_net_mma(
    const float* __restrict__ states,
    const float* __restrict__ edges,
    const float* __restrict__ bg,
    float* __restrict__ out)
{
    extern __shared__ char sm[];
    const uint2* EH = (const uint2*)(sm + SM_EH);
    const uint2* EL = (const uint2*)(sm + SM_EL);
    const float2* SP = (const float2*)(sm + SM_SP);

    const int tid = threadIdx.x;
    const int eb = blockIdx.x & 511;       // edge block (128 edges)
    const int cb = blockIdx.x >> 9;        // column half (512 cols)
    const int gbase = eb * 128;
    const int col0 = cb * 512;

    const int w = tid >> 5, lane = tid & 31;
    const int g = lane >> 2;               // groupID: row-in-tile / B-col
    const int q = lane & 3;                // threadID-in-group

    // ---- W + bias fragments -> registers (coalesced, L2-resident) ----
    uint2 wh[8], wl[8];
    float2 b2[8];
    #pragma unroll
    for (int ct = 0; ct < 8; ct++) {
        int n = col0 + w * 64 + ct * 8 + g;
        wh[ct] = d_Wh[n * 4 + q];
        wl[ct] = d_Wl[n * 4 + q];
        b2[ct] = *(const float2*)(bg + col0 + w * 64 + ct * 8 + 2 * q);
    }

    // ---- Stage + split edges: EH/EL[row][q] ----
    {
        const float2* er = (const float2*)(edges + (size_t)gbase * 16);
        #pragma unroll
        for (int k = 0; k < 2; k++) {
            int item = tid + k * 256;          // 0..511 over [row][q]
            int row = item >> 2, qq = item & 3;
            float2 v0 = er[row * 8 + qq];
            float2 v1 = er[row * 8 + qq + 4];
            __half h0, l0, h1, l1, h2v, l2, h3, l3;
            split16(v0.x, h0, l0);  split16(v0.y, h1, l1);
            split16(v1.x, h2v, l2); split16(v1.y, h3, l3);
            ((uint2*)(sm + SM_EH))[item] = make_uint2(pack_h2(h0, h1), pack_h2(h2v, h3));
            ((uint2*)(sm + SM_EL))[item] = make_uint2(pack_h2(l0, l1), pack_h2(l2, l3));
        }
    }
    // ---- Stage states: SP[a][row][q2] = {s[row][8a+2q2], s[row][8a+2q2+1]} ----
    // One float4 of input (j0=4*f4, j0&7 in {0,4}) lands on 4 contiguous floats.
    {
        const float4* sv = (const float4*)(states + (size_t)gbase * 32);
        #pragma unroll
        for (int k = 0; k < 4; k++) {
            int idx = tid + k * 256;           // 0..1023 over [row][f4]
            int row = idx >> 3, f4 = idx & 7;
            float4 v = sv[idx];
            int a = f4 >> 1, q2 = (f4 & 1) * 2;
            *(float4*)((float*)(sm + SM_SP) + ((a * 128 + row) * 4 + q2) * 2) = v;
        }
    }
    __syncthreads();

    #pragma unroll
    for (int pass = 0; pass < 4; pass++) {
        const int rb = pass * 32;

        uint2 ah[2][2], al[2][2];              // [rt][row / row+8]
        #pragma unroll
        for (int rt = 0; rt < 2; rt++) {
            int row = rb + rt * 16 + g;
            ah[rt][0] = EH[row * 4 + q];
            ah[rt][1] = EH[(row + 8) * 4 + q];
            al[rt][0] = EL[row * 4 + q];
            al[rt][1] = EL[(row + 8) * 4 + q];
        }

        float mm[2][2][2] = {};                // [ip][rt][row-half]

        #pragma unroll
        for (int a = 0; a < 4; a++) {
            float2 s0[2], s1[2];
            #pragma unroll
            for (int rt = 0; rt < 2; rt++) {
                int row = rb + rt * 16 + g;
                s0[rt] = SP[a * 512 + row * 4 + q];
                s1[rt] = SP[a * 512 + (row + 8) * 4 + q];
            }

            #pragma unroll
            for (int ip = 0; ip < 2; ip++) {
                const int ct = ip * 4 + a;
                float d[2][4];
                #pragma unroll
                for (int rt = 0; rt < 2; rt++) {
                    d[rt][0] = b2[ct].x; d[rt][1] = b2[ct].y;
                    d[rt][2] = b2[ct].x; d[rt][3] = b2[ct].y;
                }

                mma16(d[0][0], d[0][1], d[0][2], d[0][3], ah[0][0], ah[0][1], wh[ct]);
                mma16(d[1][0], d[1][1], d[1][2], d[1][3], ah[1][0], ah[1][1], wh[ct]);
                mma16(d[0][0], d[0][1], d[0][2], d[0][3], ah[0][0], ah[0][1], wl[ct]);
                mma16(d[1][0], d[1][1], d[1][2], d[1][3], ah[1][0], ah[1][1], wl[ct]);
                mma16(d[0][0], d[0][1], d[0][2], d[0][3], al[0][0], al[0][1], wh[ct]);
                mma16(d[1][0], d[1][1], d[1][2], d[1][3], al[1][0], al[1][1], wh[ct]);

                #pragma unroll
                for (int rt = 0; rt < 2; rt++) {
                    mm[ip][rt][0] = fmaf(fmaxf(d[rt][0], 0.f), s0[rt].x, mm[ip][rt][0]);
                    mm[ip][rt][0] = fmaf(fmaxf(d[rt][1], 0.f), s0[rt].y, mm[ip][rt][0]);
                    mm[ip][rt][1] = fmaf(fmaxf(d[rt][2], 0.f), s1[rt].x, mm[ip][rt][1]);
                    mm[ip][rt][1] = fmaf(fmaxf(d[rt][3], 0.f), s1[rt].y, mm[ip][rt][1]);
                }
            }
        }

        // ---- Outputs for this pass ----
        #pragma unroll
        for (int ip = 0; ip < 2; ip++) {
            const int i = cb * 16 + w * 2 + ip;
            #pragma unroll
            for (int rt = 0; rt < 2; rt++) {
                float v0 = mm[ip][rt][0], v1 = mm[ip][rt][1];
                v0 += __shfl_xor_sync(0xffffffffu, v0, 1);
                v0 += __shfl_xor_sync(0xffffffffu, v0, 2);
                v1 += __shfl_xor_sync(0xffffffffu, v1, 1);
                v1 += __shfl_xor_sync(0xffffffffu, v1, 2);
                if (q == 0) {
                    int row = rb + rt * 16 + g;
                    out[(size_t)(gbase + row) * 32 + i] = v0;
                    out[(size_t)(gbase + row + 8) * 32 + i] = v1;
                }
            }
        }
    }
}

extern "C" void kernel_launch(void* const* d_in, const int* in_sizes, int n_in,
                              void* d_out, int out_size)
{
    const float* states = (const float*)d_in[0];  // [16, 4096, 32]
    const float* edges  = (const float*)d_in[1];  // [16, 4096, 16]
    const float* W      = (const float*)d_in[2];  // [16, 1024]
    const float* b      = (const float*)d_in[3];  // [1024]
    float* out          = (float*)d_out;          // [16, 4096, 32]

    (void)in_sizes; (void)n_in; (void)out_size;

    static int configured = 0;
    if (!configured) {
        cudaFuncSetAttribute(edge_net_mma,
                             cudaFuncAttributeMaxDynamicSharedMemorySize, SM_TOTAL);
        configured = 1;
    }
    prep_w<<<16, 256>>>(W);
    edge_net_mma<<<1024, NTHREADS, SM_TOTAL>>>(states, edges, b, out);
}